// round 3
// baseline (speedup 1.0000x reference)
#include <cuda_runtime.h>
#include <math.h>

#define Bn 4096
#define Dn 128
#define Cn 512
#define EPSF 1e-5f
// total = B + C*EPS
#define TOTALF (4096.0f + 512.0f * 1e-5f)

// ---- scratch (device globals; no allocation allowed) ----
__device__ float g_mean[Cn * Dn];
__device__ float g_logprior[Cn];
__device__ float g_bias[Cn];
__device__ float g_dz[Bn * Dn];
__device__ float g_pp[128 * Dn * Dn];   // partial Gram sums
__device__ float g_pooled[Dn * Dn];
__device__ float g_prec[Dn * Dn];
__device__ float g_Pz[Bn * Dn];
__device__ float g_zPz[Bn];

// ------------------------------------------------------------------
// K1: per-class counts + means (deterministic gather, no atomics)
// 512 blocks (one per class) x 128 threads (one per dim)
// ------------------------------------------------------------------
__global__ void k_stats(const float* __restrict__ z, const int* __restrict__ y) {
    int c = blockIdx.x, j = threadIdx.x;
    __shared__ int sy[128];
    float sum = 0.f, cnt = 0.f;
    for (int b0 = 0; b0 < Bn; b0 += 128) {
        __syncthreads();
        sy[j] = y[b0 + j];
        __syncthreads();
#pragma unroll 8
        for (int i = 0; i < 128; i++) {
            if (sy[i] == c) { sum += z[(b0 + i) * Dn + j]; cnt += 1.f; }
        }
    }
    float ce = cnt + EPSF;
    g_mean[c * Dn + j] = sum / ce;
    if (j == 0) g_logprior[c] = logf(ce) - logf(TOTALF);
}

// ------------------------------------------------------------------
// K2: dz[b] = z[b] - mean[y[b]]
// ------------------------------------------------------------------
__global__ void k_dz(const float* __restrict__ z, const int* __restrict__ y) {
    int b = blockIdx.x, j = threadIdx.x;
    int c = y[b];
    g_dz[b * Dn + j] = z[b * Dn + j] - g_mean[c * Dn + j];
}

// ------------------------------------------------------------------
// K3: partial Gram matrices: block p sums rows [32p, 32p+32)
// 128 blocks x 256 threads; each thread owns an 8x8 scatter tile
// rows ty*8+i, cols tx + 16*j  (interleaved cols -> conflict-free LDS)
// ------------------------------------------------------------------
__global__ void k_gram_part() {
    int blk = blockIdx.x;
    int tid = threadIdx.x;
    int ty = tid >> 4, tx = tid & 15;
    __shared__ float srow[32 * 128];
    for (int e = tid; e < 32 * 128; e += 256) srow[e] = g_dz[blk * 32 * 128 + e];
    __syncthreads();
    float acc[8][8];
#pragma unroll
    for (int i = 0; i < 8; i++)
#pragma unroll
        for (int j = 0; j < 8; j++) acc[i][j] = 0.f;
    for (int bb = 0; bb < 32; bb++) {
        float rA[8], rB[8];
#pragma unroll
        for (int i = 0; i < 8; i++) rA[i] = srow[bb * 128 + ty * 8 + i];
#pragma unroll
        for (int j = 0; j < 8; j++) rB[j] = srow[bb * 128 + tx + 16 * j];
#pragma unroll
        for (int i = 0; i < 8; i++)
#pragma unroll
            for (int j = 0; j < 8; j++) acc[i][j] += rA[i] * rB[j];
    }
    float* dst = g_pp + blk * (Dn * Dn);
#pragma unroll
    for (int i = 0; i < 8; i++)
#pragma unroll
        for (int j = 0; j < 8; j++)
            dst[(ty * 8 + i) * 128 + tx + 16 * j] = acc[i][j];
}

// ------------------------------------------------------------------
// K4: reduce partials -> pooled = sum/total + EPS*I
// ------------------------------------------------------------------
__global__ void k_gram_red() {
    int idx = blockIdx.x * 256 + threadIdx.x;   // 64 blocks
    float s = 0.f;
#pragma unroll 4
    for (int p = 0; p < 128; p++) s += g_pp[p * (Dn * Dn) + idx];
    int i = idx >> 7, j = idx & 127;
    g_pooled[idx] = s * (1.0f / TOTALF) + (i == j ? EPSF : 0.f);
}

// ------------------------------------------------------------------
// K5: 128x128 SPD inverse, in-register Gauss-Jordan (no pivoting).
// 1024 threads: row = tid>>3 (0..127), grp = tid&7 (0..7).
// Thread owns 32 cols of augmented [A | I] row (cols 0..255).
// Active-window: at step k only groups [gk, gk+4] hold nonzeros.
// ------------------------------------------------------------------
__global__ void __launch_bounds__(1024) k_invert() {
    int tid = threadIdx.x;
    int row = tid >> 3, grp = tid & 7;
    float r[32];
    if (grp < 4) {
#pragma unroll
        for (int t = 0; t < 32; t++) r[t] = g_pooled[row * 128 + grp * 32 + t];
    } else {
        int cbase = (grp - 4) * 32;
#pragma unroll
        for (int t = 0; t < 32; t++) r[t] = (row == cbase + t) ? 1.f : 0.f;
    }
    __shared__ float s_row[256];
    __shared__ float s_f[128];
    __shared__ float s_piv;

    for (int k = 0; k < 128; k++) {
        int gk = k >> 5;
        bool active = (grp >= gk) && (grp <= gk + 4);
        __syncthreads();
        if (grp == gk) {
            if (row == k) s_piv = r[k & 31];
            else          s_f[row] = r[k & 31];
        }
        if (row == k && active) {
#pragma unroll
            for (int t = 0; t < 32; t++) s_row[grp * 32 + t] = r[t];
        }
        __syncthreads();
        float pinv = 1.0f / s_piv;
        if (row == k) {
            if (active) {
#pragma unroll
                for (int t = 0; t < 32; t++) r[t] *= pinv;
            }
        } else if (active) {
            float cf = s_f[row] * pinv;
#pragma unroll
            for (int t = 0; t < 32; t++) r[t] -= cf * s_row[grp * 32 + t];
        }
    }
    __syncthreads();
    if (grp >= 4) {
#pragma unroll
        for (int t = 0; t < 32; t++)
            g_prec[row * 128 + (grp - 4) * 32 + t] = r[t];
    }
}

// ------------------------------------------------------------------
// K6: q[c] = mean_c^T P mean_c ; bias[c] = logprior[c] - 0.5 q[c]
// 512 blocks x 128 threads
// ------------------------------------------------------------------
__global__ void k_qbias() {
    int c = blockIdx.x, j = threadIdx.x;
    __shared__ float sm[128];
    __shared__ float sred[128];
    sm[j] = g_mean[c * Dn + j];
    __syncthreads();
    float pj = 0.f;
#pragma unroll 4
    for (int d = 0; d < 128; d++) pj += sm[d] * g_prec[d * 128 + j];
    sred[j] = pj * sm[j];
    __syncthreads();
    for (int s = 64; s > 0; s >>= 1) {
        if (j < s) sred[j] += sred[j + s];
        __syncthreads();
    }
    if (j == 0) g_bias[c] = g_logprior[c] - 0.5f * sred[0];
}

// ------------------------------------------------------------------
// K7: Pz = z @ P   (P symmetric). 256 blocks x 128 threads,
// 16 z-rows per block, P tiled 32xD through smem.
// ------------------------------------------------------------------
__global__ void k_pz(const float* __restrict__ z) {
    int b0 = blockIdx.x * 16;
    int j = threadIdx.x;
    __shared__ float sP[32 * 128];
    __shared__ float sz[16 * 33];
    float acc[16];
#pragma unroll
    for (int t = 0; t < 16; t++) acc[t] = 0.f;

    for (int d0 = 0; d0 < 128; d0 += 32) {
        __syncthreads();
#pragma unroll
        for (int dd = 0; dd < 32; dd++)
            sP[dd * 128 + j] = g_prec[(d0 + dd) * 128 + j];
        for (int e = j; e < 16 * 32; e += 128) {
            int rr = e >> 5, dd = e & 31;
            sz[rr * 33 + dd] = z[(b0 + rr) * Dn + d0 + dd];
        }
        __syncthreads();
        for (int dd = 0; dd < 32; dd++) {
            float pv = sP[dd * 128 + j];
#pragma unroll
            for (int rr = 0; rr < 16; rr++) acc[rr] += sz[rr * 33 + dd] * pv;
        }
    }
#pragma unroll
    for (int rr = 0; rr < 16; rr++) g_Pz[(b0 + rr) * Dn + j] = acc[rr];
}

// ------------------------------------------------------------------
// K8: zPz[b] = dot(Pz[b], z[b]). 1024 blocks x 128 thr, warp/row.
// ------------------------------------------------------------------
__global__ void k_zpz(const float* __restrict__ z) {
    int warp = threadIdx.x >> 5, lane = threadIdx.x & 31;
    int rr = blockIdx.x * 4 + warp;
    float s = 0.f;
#pragma unroll
    for (int kk = lane; kk < 128; kk += 32)
        s += g_Pz[rr * Dn + kk] * z[rr * Dn + kk];
#pragma unroll
    for (int o = 16; o; o >>= 1) s += __shfl_xor_sync(0xffffffffu, s, o);
    if (lane == 0) g_zPz[rr] = s;
}

// ------------------------------------------------------------------
// K9: out[b,c] = Pz[b].mean[c] + bias[c] - 0.5 zPz[b]
// Tiled 64x64 GEMM, 4x4 register tiles, transposed+padded smem.
// grid (8 c-tiles, 64 b-tiles) x 256 threads
// ------------------------------------------------------------------
__global__ void k_out(float* __restrict__ out) {
    int bx = blockIdx.x, by = blockIdx.y;
    int tid = threadIdx.x;
    int tx = tid & 15, ty = tid >> 4;
    __shared__ float sA[32 * 65];
    __shared__ float sB[32 * 65];
    float acc[4][4];
#pragma unroll
    for (int i = 0; i < 4; i++)
#pragma unroll
        for (int j = 0; j < 4; j++) acc[i][j] = 0.f;

    for (int d0 = 0; d0 < 128; d0 += 32) {
        __syncthreads();
        for (int e = tid; e < 2048; e += 256) {
            int rr = e >> 5, dd = e & 31;
            sA[dd * 65 + rr] = g_Pz[(by * 64 + rr) * Dn + d0 + dd];
            sB[dd * 65 + rr] = g_mean[(bx * 64 + rr) * Dn + d0 + dd];
        }
        __syncthreads();
        for (int dd = 0; dd < 32; dd++) {
            float rA[4], rB[4];
#pragma unroll
            for (int i = 0; i < 4; i++) rA[i] = sA[dd * 65 + ty * 4 + i];
#pragma unroll
            for (int j = 0; j < 4; j++) rB[j] = sB[dd * 65 + tx * 4 + j];
#pragma unroll
            for (int i = 0; i < 4; i++)
#pragma unroll
                for (int j = 0; j < 4; j++) acc[i][j] += rA[i] * rB[j];
        }
    }
    float zr[4], bc[4];
#pragma unroll
    for (int i = 0; i < 4; i++) zr[i] = g_zPz[by * 64 + ty * 4 + i];
#pragma unroll
    for (int j = 0; j < 4; j++) bc[j] = g_bias[bx * 64 + tx * 4 + j];
#pragma unroll
    for (int i = 0; i < 4; i++) {
        int rr = by * 64 + ty * 4 + i;
        float4 v;
        v.x = acc[i][0] + bc[0] - 0.5f * zr[i];
        v.y = acc[i][1] + bc[1] - 0.5f * zr[i];
        v.z = acc[i][2] + bc[2] - 0.5f * zr[i];
        v.w = acc[i][3] + bc[3] - 0.5f * zr[i];
        *reinterpret_cast<float4*>(&out[rr * Cn + bx * 64 + tx * 4]) = v;
    }
}

// ------------------------------------------------------------------
extern "C" void kernel_launch(void* const* d_in, const int* in_sizes, int n_in,
                              void* d_out, int out_size) {
    const float* z;
    const int* y;
    if (in_sizes[0] == Bn * Dn) {
        z = (const float*)d_in[0];
        y = (const int*)d_in[1];
    } else {
        z = (const float*)d_in[1];
        y = (const int*)d_in[0];
    }
    float* out = (float*)d_out;

    k_stats<<<Cn, 128>>>(z, y);
    k_dz<<<Bn, 128>>>(z, y);
    k_gram_part<<<128, 256>>>();
    k_gram_red<<<64, 256>>>();
    k_invert<<<1, 1024>>>();
    k_qbias<<<Cn, 128>>>();
    k_pz<<<Bn / 16, 128>>>(z);
    k_zpz<<<Bn / 4, 128>>>(z);
    k_out<<<dim3(8, 64), 256>>>(out);
}